// round 2
// baseline (speedup 1.0000x reference)
#include <cuda_runtime.h>
#include <math.h>

// Problem constants: B=8, N=4096, C=768, H=8, D=96
constexpr int M_TOK = 8 * 4096;   // 32768 tokens
constexpr int K_IN  = 768;        // C
constexpr int D_G   = 96;         // per-head dim

// ---- device scratch (allocation-free rule: use __device__ globals) ----
__device__ float g_Wr[96 * 768];   // w1 * sum_h W_qkv_rgb[1536 + h*96 + d, :]
__device__ float g_Wd[96 * 768];   // w0 * sum_h W_qkv_depth[768 + h*96 + d, :]
__device__ float g_bg[96];         // combined bias for g
__device__ float g_Wf[768 * 96];   // Wout folded over heads: sum_q W_out[c, q*96+d]
__device__ float g_G[32768 * 96];  // intermediate g[n,d]

// ============================================================
// Prep: fold heads into the weights (tiny, ~0.5 MFLOP)
// ============================================================
__global__ void prep_kernel(const float* __restrict__ W1, const float* __restrict__ b1,
                            const float* __restrict__ W2, const float* __restrict__ b2,
                            const float* __restrict__ Wout, const float* __restrict__ aw)
{
    int idx = blockIdx.x * blockDim.x + threadIdx.x;   // 0 .. 73727
    float w0 = 1.0f / (1.0f + expf(-aw[0]));
    float w1 = 1.0f / (1.0f + expf(-aw[1]));

    if (idx < 96 * 768) {
        int d = idx / 768;
        int c = idx - d * 768;
        float sr = 0.0f, sd = 0.0f;
#pragma unroll
        for (int h = 0; h < 8; h++) {
            sr += W1[(size_t)(1536 + h * 96 + d) * 768 + c];
            sd += W2[(size_t)(768  + h * 96 + d) * 768 + c];
        }
        g_Wr[idx] = w1 * sr;   // wv_depth = attn_depth @ v_rgb  -> weighted by w1
        g_Wd[idx] = w0 * sd;   // wv_rgb   = attn_rgb   @ v_depth -> weighted by w0
    }
    if (idx < 768 * 96) {
        int c = idx / 96;
        int d = idx - c * 96;
        float s = 0.0f;
#pragma unroll
        for (int q = 0; q < 8; q++) s += Wout[(size_t)c * 768 + q * 96 + d];
        g_Wf[idx] = s;
    }
    if (idx < 96) {
        float sbr = 0.0f, sbd = 0.0f;
#pragma unroll
        for (int h = 0; h < 8; h++) {
            sbr += b1[1536 + h * 96 + idx];
            sbd += b2[768  + h * 96 + idx];
        }
        g_bg[idx] = w0 * sbd + w1 * sbr;
    }
}

// ============================================================
// GEMM-G:  G[32768, 96] = Xr @ g_Wr^T + Xd @ g_Wd^T + g_bg
// Virtual K = 1536 (first 768 from rgb, next 768 from depth).
// BM=64, BN=96(all), BK=32, 128 threads, 8x6 microtile.
// ============================================================
__global__ __launch_bounds__(128) void gemm_g(const float* __restrict__ Xr,
                                              const float* __restrict__ Xd)
{
    __shared__ float As[32][68];   // k-major, padded (68*4B = 16B-mult for f4 reads)
    __shared__ float Bs[32][97];   // k-major, odd pad -> conflict-free scalar access

    const int tid = threadIdx.x;
    const int tx  = tid & 15;      // 16 col-groups * 6 = 96
    const int ty  = tid >> 4;      // 8 row-groups * 8 = 64
    const int bm  = blockIdx.x << 6;

    float acc[8][6];
#pragma unroll
    for (int i = 0; i < 8; i++)
#pragma unroll
        for (int j = 0; j < 6; j++) acc[i][j] = 0.0f;

    for (int t = 0; t < 48; t++) {
        const float* X = (t < 24) ? Xr : Xd;
        const float* W = (t < 24) ? g_Wr : g_Wd;
        const int kb = (t < 24) ? (t << 5) : ((t - 24) << 5);

        // A tile: 64 rows x 32 k  (512 float4, 4/thread)
#pragma unroll
        for (int l = 0; l < 4; l++) {
            int f = tid + (l << 7);
            int r = f >> 3, c4 = f & 7;
            float4 v = *reinterpret_cast<const float4*>(X + (size_t)(bm + r) * 768 + kb + (c4 << 2));
            As[(c4 << 2) + 0][r] = v.x;
            As[(c4 << 2) + 1][r] = v.y;
            As[(c4 << 2) + 2][r] = v.z;
            As[(c4 << 2) + 3][r] = v.w;
        }
        // B tile: 96 rows x 32 k  (768 float4, 6/thread)
#pragma unroll
        for (int l = 0; l < 6; l++) {
            int f = tid + (l << 7);
            int r = f >> 3, c4 = f & 7;
            float4 v = *reinterpret_cast<const float4*>(W + (size_t)r * 768 + kb + (c4 << 2));
            Bs[(c4 << 2) + 0][r] = v.x;
            Bs[(c4 << 2) + 1][r] = v.y;
            Bs[(c4 << 2) + 2][r] = v.z;
            Bs[(c4 << 2) + 3][r] = v.w;
        }
        __syncthreads();

#pragma unroll
        for (int k = 0; k < 32; k++) {
            float4 a0 = *reinterpret_cast<const float4*>(&As[k][ty << 3]);
            float4 a1 = *reinterpret_cast<const float4*>(&As[k][(ty << 3) + 4]);
            float ra[8] = {a0.x, a0.y, a0.z, a0.w, a1.x, a1.y, a1.z, a1.w};
            float rb[6];
#pragma unroll
            for (int j = 0; j < 6; j++) rb[j] = Bs[k][tx * 6 + j];
#pragma unroll
            for (int i = 0; i < 8; i++)
#pragma unroll
                for (int j = 0; j < 6; j++)
                    acc[i][j] = fmaf(ra[i], rb[j], acc[i][j]);
        }
        __syncthreads();
    }

#pragma unroll
    for (int i = 0; i < 8; i++) {
        int m = bm + (ty << 3) + i;
#pragma unroll
        for (int j = 0; j < 6; j++) {
            int n = tx * 6 + j;
            g_G[(size_t)m * 96 + n] = acc[i][j] + g_bg[n];
        }
    }
}

// ============================================================
// GEMM-out: Y[32768, 768] = G @ g_Wf^T + b_out   (K = 96)
// BM=128, BN=128, BK=32, 256 threads, 8x8 microtile.
// ============================================================
__global__ __launch_bounds__(256) void gemm_out(const float* __restrict__ bout,
                                                float* __restrict__ Y)
{
    __shared__ float As[32][132];  // k-major, 132*4B is 16B-mult
    __shared__ float Bs[32][132];

    const int tid = threadIdx.x;
    const int tx  = tid & 15;
    const int ty  = tid >> 4;
    const int bm  = blockIdx.y << 7;
    const int bn  = blockIdx.x << 7;

    float acc[8][8];
#pragma unroll
    for (int i = 0; i < 8; i++)
#pragma unroll
        for (int j = 0; j < 8; j++) acc[i][j] = 0.0f;

    for (int t = 0; t < 3; t++) {
        const int kt = t << 5;
        // 128 rows x 32 k each for A and B: 1024 float4 -> 4/thread each
#pragma unroll
        for (int l = 0; l < 4; l++) {
            int f = tid + (l << 8);
            int r = f >> 3, c4 = f & 7;
            float4 v = *reinterpret_cast<const float4*>(g_G + (size_t)(bm + r) * 96 + kt + (c4 << 2));
            As[(c4 << 2) + 0][r] = v.x;
            As[(c4 << 2) + 1][r] = v.y;
            As[(c4 << 2) + 2][r] = v.z;
            As[(c4 << 2) + 3][r] = v.w;
            float4 w = *reinterpret_cast<const float4*>(g_Wf + (size_t)(bn + r) * 96 + kt + (c4 << 2));
            Bs[(c4 << 2) + 0][r] = w.x;
            Bs[(c4 << 2) + 1][r] = w.y;
            Bs[(c4 << 2) + 2][r] = w.z;
            Bs[(c4 << 2) + 3][r] = w.w;
        }
        __syncthreads();

#pragma unroll
        for (int k = 0; k < 32; k++) {
            float4 a0 = *reinterpret_cast<const float4*>(&As[k][ty << 3]);
            float4 a1 = *reinterpret_cast<const float4*>(&As[k][(ty << 3) + 4]);
            float4 b0 = *reinterpret_cast<const float4*>(&Bs[k][tx << 3]);
            float4 b1 = *reinterpret_cast<const float4*>(&Bs[k][(tx << 3) + 4]);
            float ra[8] = {a0.x, a0.y, a0.z, a0.w, a1.x, a1.y, a1.z, a1.w};
            float rb[8] = {b0.x, b0.y, b0.z, b0.w, b1.x, b1.y, b1.z, b1.w};
#pragma unroll
            for (int i = 0; i < 8; i++)
#pragma unroll
                for (int j = 0; j < 8; j++)
                    acc[i][j] = fmaf(ra[i], rb[j], acc[i][j]);
        }
        __syncthreads();
    }

#pragma unroll
    for (int i = 0; i < 8; i++) {
        int m = bm + (ty << 3) + i;
        int n0 = bn + (tx << 3);
        float4 o0, o1;
        o0.x = acc[i][0] + bout[n0 + 0];
        o0.y = acc[i][1] + bout[n0 + 1];
        o0.z = acc[i][2] + bout[n0 + 2];
        o0.w = acc[i][3] + bout[n0 + 3];
        o1.x = acc[i][4] + bout[n0 + 4];
        o1.y = acc[i][5] + bout[n0 + 5];
        o1.z = acc[i][6] + bout[n0 + 6];
        o1.w = acc[i][7] + bout[n0 + 7];
        *reinterpret_cast<float4*>(Y + (size_t)m * 768 + n0)     = o0;
        *reinterpret_cast<float4*>(Y + (size_t)m * 768 + n0 + 4) = o1;
    }
}

// ============================================================
// Copy x_rgb -> first half of output (identity passthrough)
// ============================================================
__global__ void copy_rgb(const float4* __restrict__ src, float4* __restrict__ dst)
{
    size_t i = (size_t)blockIdx.x * blockDim.x + threadIdx.x;
    dst[i] = src[i];
}

// ============================================================
extern "C" void kernel_launch(void* const* d_in, const int* in_sizes, int n_in,
                              void* d_out, int out_size)
{
    const float* x_rgb   = (const float*)d_in[0];
    const float* x_depth = (const float*)d_in[1];
    const float* W1      = (const float*)d_in[2];
    const float* b1      = (const float*)d_in[3];
    const float* W2      = (const float*)d_in[4];
    const float* b2      = (const float*)d_in[5];
    const float* Wout    = (const float*)d_in[6];
    const float* bout    = (const float*)d_in[7];
    const float* aw      = (const float*)d_in[8];

    float* out_rgb = (float*)d_out;
    float* out_fus = out_rgb + (size_t)M_TOK * K_IN;   // second half: x_fusion

    prep_kernel<<<288, 256>>>(W1, b1, W2, b2, Wout, aw);
    gemm_g<<<M_TOK / 64, 128>>>(x_rgb, x_depth);
    gemm_out<<<dim3(K_IN / 128, M_TOK / 128), 256>>>(bout, out_fus);
    copy_rgb<<<(M_TOK * K_IN / 4) / 256, 256>>>((const float4*)x_rgb, (float4*)out_rgb);
}

// round 3
// speedup vs baseline: 1.0523x; 1.0523x over previous
#include <cuda_runtime.h>
#include <math.h>

// Problem constants: B=8, N=4096, C=768, H=8, D=96
constexpr int M_TOK = 8 * 4096;   // 32768 tokens
constexpr int K_IN  = 768;        // C
constexpr int D_G   = 96;         // per-head dim

// ---- device scratch (allocation-free rule: use __device__ globals) ----
__device__ float g_Wr[96 * 768];   // w1 * sum_h W_qkv_rgb[1536 + h*96 + d, :]
__device__ float g_Wd[96 * 768];   // w0 * sum_h W_qkv_depth[768 + h*96 + d, :]
__device__ float g_bg[96];         // combined bias for g
__device__ float g_Wf[768 * 96];   // Wout folded over heads: sum_q W_out[c, q*96+d]
__device__ float g_G[32768 * 96];  // intermediate g[n,d]

// ============================================================
// Prep: fold heads into the weights (tiny, ~0.5 MFLOP)
// ============================================================
__global__ void prep_kernel(const float* __restrict__ W1, const float* __restrict__ b1,
                            const float* __restrict__ W2, const float* __restrict__ b2,
                            const float* __restrict__ Wout, const float* __restrict__ aw)
{
    int idx = blockIdx.x * blockDim.x + threadIdx.x;   // 0 .. 73727
    float w0 = 1.0f / (1.0f + expf(-aw[0]));
    float w1 = 1.0f / (1.0f + expf(-aw[1]));

    if (idx < 96 * 768) {
        int d = idx / 768;
        int c = idx - d * 768;
        float sr = 0.0f, sd = 0.0f;
#pragma unroll
        for (int h = 0; h < 8; h++) {
            sr += W1[(size_t)(1536 + h * 96 + d) * 768 + c];
            sd += W2[(size_t)(768  + h * 96 + d) * 768 + c];
        }
        g_Wr[idx] = w1 * sr;   // wv_depth = attn_depth @ v_rgb  -> weighted by w1
        g_Wd[idx] = w0 * sd;   // wv_rgb   = attn_rgb   @ v_depth -> weighted by w0
    }
    if (idx < 768 * 96) {
        int c = idx / 96;
        int d = idx - c * 96;
        float s = 0.0f;
#pragma unroll
        for (int q = 0; q < 8; q++) s += Wout[(size_t)c * 768 + q * 96 + d];
        g_Wf[idx] = s;
    }
    if (idx < 96) {
        float sbr = 0.0f, sbd = 0.0f;
#pragma unroll
        for (int h = 0; h < 8; h++) {
            sbr += b1[1536 + h * 96 + idx];
            sbd += b2[768  + h * 96 + idx];
        }
        g_bg[idx] = w0 * sbd + w1 * sbr;
    }
}

// ============================================================
// GEMM-G:  G[32768, 96] = Xr @ g_Wr^T + Xd @ g_Wd^T + g_bg
// Virtual K = 1536 (first 768 from rgb, next 768 from depth).
// BM=64, BN=96(all), BK=32, 128 threads, 8x6 microtile.
// ============================================================
__global__ __launch_bounds__(128) void gemm_g(const float* __restrict__ Xr,
                                              const float* __restrict__ Xd)
{
    __shared__ float As[32][68];   // k-major, padded (68*4B = 16B-mult for f4 reads)
    __shared__ float Bs[32][97];   // k-major, odd pad -> conflict-free scalar access

    const int tid = threadIdx.x;
    const int tx  = tid & 15;      // 16 col-groups * 6 = 96
    const int ty  = tid >> 4;      // 8 row-groups * 8 = 64
    const int bm  = blockIdx.x << 6;

    float acc[8][6];
#pragma unroll
    for (int i = 0; i < 8; i++)
#pragma unroll
        for (int j = 0; j < 6; j++) acc[i][j] = 0.0f;

    for (int t = 0; t < 48; t++) {
        const float* X = (t < 24) ? Xr : Xd;
        const float* W = (t < 24) ? g_Wr : g_Wd;
        const int kb = (t < 24) ? (t << 5) : ((t - 24) << 5);

        // A tile: 64 rows x 32 k  (512 float4, 4/thread)
#pragma unroll
        for (int l = 0; l < 4; l++) {
            int f = tid + (l << 7);
            int r = f >> 3, c4 = f & 7;
            float4 v = *reinterpret_cast<const float4*>(X + (size_t)(bm + r) * 768 + kb + (c4 << 2));
            As[(c4 << 2) + 0][r] = v.x;
            As[(c4 << 2) + 1][r] = v.y;
            As[(c4 << 2) + 2][r] = v.z;
            As[(c4 << 2) + 3][r] = v.w;
        }
        // B tile: 96 rows x 32 k  (768 float4, 6/thread)
#pragma unroll
        for (int l = 0; l < 6; l++) {
            int f = tid + (l << 7);
            int r = f >> 3, c4 = f & 7;
            float4 v = *reinterpret_cast<const float4*>(W + (size_t)r * 768 + kb + (c4 << 2));
            Bs[(c4 << 2) + 0][r] = v.x;
            Bs[(c4 << 2) + 1][r] = v.y;
            Bs[(c4 << 2) + 2][r] = v.z;
            Bs[(c4 << 2) + 3][r] = v.w;
        }
        __syncthreads();

#pragma unroll
        for (int k = 0; k < 32; k++) {
            float4 a0 = *reinterpret_cast<const float4*>(&As[k][ty << 3]);
            float4 a1 = *reinterpret_cast<const float4*>(&As[k][(ty << 3) + 4]);
            float ra[8] = {a0.x, a0.y, a0.z, a0.w, a1.x, a1.y, a1.z, a1.w};
            float rb[6];
#pragma unroll
            for (int j = 0; j < 6; j++) rb[j] = Bs[k][tx * 6 + j];
#pragma unroll
            for (int i = 0; i < 8; i++)
#pragma unroll
                for (int j = 0; j < 6; j++)
                    acc[i][j] = fmaf(ra[i], rb[j], acc[i][j]);
        }
        __syncthreads();
    }

#pragma unroll
    for (int i = 0; i < 8; i++) {
        int m = bm + (ty << 3) + i;
#pragma unroll
        for (int j = 0; j < 6; j++) {
            int n = tx * 6 + j;
            g_G[(size_t)m * 96 + n] = acc[i][j] + g_bg[n];
        }
    }
}

// ============================================================
// GEMM-out: Y[32768, 768] = G @ g_Wf^T + b_out   (K = 96)
// BM=128, BN=128, BK=32, 256 threads, 8x8 microtile.
// ============================================================
__global__ __launch_bounds__(256) void gemm_out(const float* __restrict__ bout,
                                                float* __restrict__ Y)
{
    __shared__ float As[32][132];  // k-major, 132*4B is 16B-mult
    __shared__ float Bs[32][132];

    const int tid = threadIdx.x;
    const int tx  = tid & 15;
    const int ty  = tid >> 4;
    const int bm  = blockIdx.y << 7;
    const int bn  = blockIdx.x << 7;

    float acc[8][8];
#pragma unroll
    for (int i = 0; i < 8; i++)
#pragma unroll
        for (int j = 0; j < 8; j++) acc[i][j] = 0.0f;

    for (int t = 0; t < 3; t++) {
        const int kt = t << 5;
        // 128 rows x 32 k each for A and B: 1024 float4 -> 4/thread each
#pragma unroll
        for (int l = 0; l < 4; l++) {
            int f = tid + (l << 8);
            int r = f >> 3, c4 = f & 7;
            float4 v = *reinterpret_cast<const float4*>(g_G + (size_t)(bm + r) * 96 + kt + (c4 << 2));
            As[(c4 << 2) + 0][r] = v.x;
            As[(c4 << 2) + 1][r] = v.y;
            As[(c4 << 2) + 2][r] = v.z;
            As[(c4 << 2) + 3][r] = v.w;
            float4 w = *reinterpret_cast<const float4*>(g_Wf + (size_t)(bn + r) * 96 + kt + (c4 << 2));
            Bs[(c4 << 2) + 0][r] = w.x;
            Bs[(c4 << 2) + 1][r] = w.y;
            Bs[(c4 << 2) + 2][r] = w.z;
            Bs[(c4 << 2) + 3][r] = w.w;
        }
        __syncthreads();

#pragma unroll
        for (int k = 0; k < 32; k++) {
            float4 a0 = *reinterpret_cast<const float4*>(&As[k][ty << 3]);
            float4 a1 = *reinterpret_cast<const float4*>(&As[k][(ty << 3) + 4]);
            float4 b0 = *reinterpret_cast<const float4*>(&Bs[k][tx << 3]);
            float4 b1 = *reinterpret_cast<const float4*>(&Bs[k][(tx << 3) + 4]);
            float ra[8] = {a0.x, a0.y, a0.z, a0.w, a1.x, a1.y, a1.z, a1.w};
            float rb[8] = {b0.x, b0.y, b0.z, b0.w, b1.x, b1.y, b1.z, b1.w};
#pragma unroll
            for (int i = 0; i < 8; i++)
#pragma unroll
                for (int j = 0; j < 8; j++)
                    acc[i][j] = fmaf(ra[i], rb[j], acc[i][j]);
        }
        __syncthreads();
    }

#pragma unroll
    for (int i = 0; i < 8; i++) {
        int m = bm + (ty << 3) + i;
        int n0 = bn + (tx << 3);
        float4 o0, o1;
        o0.x = acc[i][0] + bout[n0 + 0];
        o0.y = acc[i][1] + bout[n0 + 1];
        o0.z = acc[i][2] + bout[n0 + 2];
        o0.w = acc[i][3] + bout[n0 + 3];
        o1.x = acc[i][4] + bout[n0 + 4];
        o1.y = acc[i][5] + bout[n0 + 5];
        o1.z = acc[i][6] + bout[n0 + 6];
        o1.w = acc[i][7] + bout[n0 + 7];
        *reinterpret_cast<float4*>(Y + (size_t)m * 768 + n0)     = o0;
        *reinterpret_cast<float4*>(Y + (size_t)m * 768 + n0 + 4) = o1;
    }
}

// ============================================================
// Copy x_rgb -> first half of output (identity passthrough)
// ============================================================
__global__ void copy_rgb(const float4* __restrict__ src, float4* __restrict__ dst)
{
    size_t i = (size_t)blockIdx.x * blockDim.x + threadIdx.x;
    dst[i] = src[i];
}

// ============================================================
extern "C" void kernel_launch(void* const* d_in, const int* in_sizes, int n_in,
                              void* d_out, int out_size)
{
    const float* x_rgb   = (const float*)d_in[0];
    const float* x_depth = (const float*)d_in[1];
    const float* W1      = (const float*)d_in[2];
    const float* b1      = (const float*)d_in[3];
    const float* W2      = (const float*)d_in[4];
    const float* b2      = (const float*)d_in[5];
    const float* Wout    = (const float*)d_in[6];
    const float* bout    = (const float*)d_in[7];
    const float* aw      = (const float*)d_in[8];

    float* out_rgb = (float*)d_out;
    float* out_fus = out_rgb + (size_t)M_TOK * K_IN;   // second half: x_fusion

    prep_kernel<<<288, 256>>>(W1, b1, W2, b2, Wout, aw);
    gemm_g<<<M_TOK / 64, 128>>>(x_rgb, x_depth);
    gemm_out<<<dim3(K_IN / 128, M_TOK / 128), 256>>>(bout, out_fus);
    copy_rgb<<<(M_TOK * K_IN / 4) / 256, 256>>>((const float4*)x_rgb, (float4*)out_rgb);
}